// round 3
// baseline (speedup 1.0000x reference)
#include <cuda_runtime.h>

// Problem constants (fixed-shape problem)
#define N_NODES 50000
#define N_EDGES 800000
#define TWO_N   100000
#define TWO_E   1600000
#define SCAN_BLK 1024
#define SCAN_NBLK ((TWO_N + SCAN_BLK - 1) / SCAN_BLK)   // 98

// ---------------- scratch (device globals; no allocation allowed) -----------
__device__ __align__(16) float g_xw[N_NODES * 256];  // x @ [W0 | W1] (51.2 MB)
__device__ __align__(16) float g_att[N_NODES * 32];  // [as0(8) ad0(8) as1(8) ad1(8)]
__device__ int   g_deg[TWO_N];            // in-degree per (hop,node)
__device__ int   g_off[TWO_N + 1];        // CSR offsets (concatenated hops)
__device__ int   g_cur[TWO_N];            // scatter cursors
__device__ int   g_srcarr[TWO_E];         // CSR: source node per edge
__device__ int   g_bsum[SCAN_NBLK];
__device__ int   g_bsum_scan[SCAN_NBLK];

// ---------------- K0: zero degree counters ----------------------------------
__global__ void zero_kernel() {
    int i = blockIdx.x * blockDim.x + threadIdx.x;
    if (i < TWO_N) g_deg[i] = 0;
}

// ---------------- K1: GEMM  g_xw = x @ [W0 | W1] ----------------------------
__global__ void gemm_kernel(const float* __restrict__ x,
                            const float* __restrict__ W0,
                            const float* __restrict__ W1) {
    __shared__ float xs[64][16];
    __shared__ float ws[16][256];
    int tid = threadIdx.x;
    int m0  = blockIdx.x * 64;
    int ct  = tid & 31;
    int rt  = tid >> 5;

    float acc[8][8];
#pragma unroll
    for (int r = 0; r < 8; r++)
#pragma unroll
        for (int c = 0; c < 8; c++) acc[r][c] = 0.f;

    for (int k0 = 0; k0 < 256; k0 += 16) {
#pragma unroll
        for (int i = 0; i < 4; i++) {
            int idx = tid + 256 * i;
            int r = idx >> 4, kk = idx & 15;
            int gr = m0 + r;
            xs[r][kk] = (gr < N_NODES) ? x[gr * 256 + k0 + kk] : 0.f;
        }
#pragma unroll
        for (int i = 0; i < 16; i++) {
            int idx = tid + 256 * i;
            int kk = idx >> 8, c = idx & 255;
            ws[kk][c] = (c < 128) ? W0[(k0 + kk) * 128 + c]
                                  : W1[(k0 + kk) * 128 + (c - 128)];
        }
        __syncthreads();
#pragma unroll
        for (int kk = 0; kk < 16; kk++) {
            float xv[8], wv[8];
#pragma unroll
            for (int r = 0; r < 8; r++) xv[r] = xs[rt * 8 + r][kk];
#pragma unroll
            for (int c = 0; c < 8; c++) wv[c] = ws[kk][ct + 32 * c];
#pragma unroll
            for (int r = 0; r < 8; r++)
#pragma unroll
                for (int c = 0; c < 8; c++) acc[r][c] += xv[r] * wv[c];
        }
        __syncthreads();
    }
#pragma unroll
    for (int r = 0; r < 8; r++) {
        int gr = m0 + rt * 8 + r;
        if (gr < N_NODES) {
#pragma unroll
            for (int c = 0; c < 8; c++)
                g_xw[gr * 256 + ct + 32 * c] = acc[r][c];
        }
    }
}

// ---------------- K2: attention logits per node -----------------------------
__global__ void att_kernel(const float* __restrict__ as0, const float* __restrict__ ad0,
                           const float* __restrict__ as1, const float* __restrict__ ad1) {
    int gw = (blockIdx.x * blockDim.x + threadIdx.x) >> 5;
    if (gw >= N_NODES) return;
    int lane = threadIdx.x & 31;
    int hop = lane >> 4;
    int l   = lane & 15;
    int h   = l >> 1;
    int co  = (l & 1) * 8;
    const float* xwrow = &g_xw[gw * 256 + hop * 128 + l * 8];
    const float* as = hop ? as1 : as0;
    const float* ad = hop ? ad1 : ad0;
    float ps = 0.f, pd = 0.f;
#pragma unroll
    for (int i = 0; i < 8; i++) {
        float v = xwrow[i];
        ps += v * as[h * 16 + co + i];
        pd += v * ad[h * 16 + co + i];
    }
    ps += __shfl_xor_sync(0xffffffffu, ps, 1);
    pd += __shfl_xor_sync(0xffffffffu, pd, 1);
    if ((l & 1) == 0) {
        g_att[gw * 32 + hop * 16 + h]     = ps;
        g_att[gw * 32 + hop * 16 + 8 + h] = pd;
    }
}

// ---------------- K3: count in-degrees for both hops ------------------------
__global__ void count_kernel(const int* __restrict__ row,
                             const int* __restrict__ col) {
    int e = blockIdx.x * blockDim.x + threadIdx.x;
    if (e >= N_EDGES) return;
    int d0 = col[e];
    atomicAdd(&g_deg[d0], 1);
    int d1 = col[d0];
    atomicAdd(&g_deg[N_NODES + d1], 1);
}

// ---------------- K4: exclusive scan (3 stages) -----------------------------
__global__ void scanA_kernel() {
    __shared__ int sh[SCAN_BLK];
    int t = threadIdx.x;
    int i = blockIdx.x * SCAN_BLK + t;
    int v = (i < TWO_N) ? g_deg[i] : 0;
    sh[t] = v;
    __syncthreads();
    for (int off = 1; off < SCAN_BLK; off <<= 1) {
        int add = (t >= off) ? sh[t - off] : 0;
        __syncthreads();
        sh[t] += add;
        __syncthreads();
    }
    if (i < TWO_N) g_off[i] = sh[t] - v;
    if (t == SCAN_BLK - 1) g_bsum[blockIdx.x] = sh[SCAN_BLK - 1];
}

__global__ void scanB_kernel() {
    if (threadIdx.x == 0) {
        int s = 0;
        for (int b = 0; b < SCAN_NBLK; b++) {
            int v = g_bsum[b];
            g_bsum_scan[b] = s;
            s += v;
        }
    }
}

__global__ void scanC_kernel() {
    int i = blockIdx.x * SCAN_BLK + threadIdx.x;
    if (i < TWO_N) {
        int v = g_off[i] + g_bsum_scan[blockIdx.x];
        g_off[i] = v;
        g_cur[i] = v;
    }
    if (i == 0) g_off[TWO_N] = TWO_E;
}

// ---------------- K5: scatter sources into CSR ------------------------------
__global__ void scatter_kernel(const int* __restrict__ row,
                               const int* __restrict__ col) {
    int e = blockIdx.x * blockDim.x + threadIdx.x;
    if (e >= N_EDGES) return;
    int r0 = row[e];
    int d0 = col[e];
    int p = atomicAdd(&g_cur[d0], 1);
    g_srcarr[p] = r0;
    int r1 = row[d0];
    int d1 = col[d0];
    p = atomicAdd(&g_cur[N_NODES + d1], 1);
    g_srcarr[p] = r1;
}

// ---------------- K6: pull aggregation (softmax over in-edges + self) -------
// Reference subtlety: hop-2 edge list gets self-loops appended TWICE (once in
// reference(), once inside _gat_conv) -> self term has weight 2 for hop 1.
// No segment-max needed: scores are O(1) so exp() is safe; softmax is
// shift-invariant so the result matches the max-stabilized reference.
__global__ void agg_kernel(const float* __restrict__ b0,
                           const float* __restrict__ b1,
                           float* __restrict__ out) {
    int gw = (blockIdx.x * blockDim.x + threadIdx.x) >> 5;
    if (gw >= TWO_N) return;
    int lane = threadIdx.x & 31;
    int hop = (gw >= N_NODES) ? 1 : 0;
    int n   = gw - hop * N_NODES;
    int head = lane >> 2;

    float a_d      = g_att[n * 32 + hop * 16 + 8 + head];
    float a_s_self = g_att[n * 32 + hop * 16 + head];

    // self loop (doubled for hop 2 — see note above)
    float t = a_s_self + a_d;
    t = (t > 0.f) ? t : 0.2f * t;
    float p = __expf(t) * (hop ? 2.0f : 1.0f);
    float sum = p;
    float4 v = *(const float4*)&g_xw[n * 256 + hop * 128 + lane * 4];
    float4 acc;
    acc.x = p * v.x; acc.y = p * v.y; acc.z = p * v.z; acc.w = p * v.w;

    int jb = g_off[gw], je = g_off[gw + 1];
    for (int j = jb; j < je; j++) {
        int src = g_srcarr[j];
        float a_s = g_att[src * 32 + hop * 16 + head];
        float tt = a_s + a_d;
        tt = (tt > 0.f) ? tt : 0.2f * tt;
        float pp = __expf(tt);
        sum += pp;
        float4 w = *(const float4*)&g_xw[src * 256 + hop * 128 + lane * 4];
        acc.x += pp * w.x; acc.y += pp * w.y;
        acc.z += pp * w.z; acc.w += pp * w.w;
    }
    float inv = 1.f / sum;
    const float* bias = hop ? b1 : b0;
    float4 bb = *(const float4*)&bias[lane * 4];
    float4 o;
    o.x = acc.x * inv + bb.x;
    o.y = acc.y * inv + bb.y;
    o.z = acc.z * inv + bb.z;
    o.w = acc.w * inv + bb.w;
    *(float4*)&out[n * 256 + hop * 128 + lane * 4] = o;
}

// ---------------- K7: residual + LayerNorm (in place over d_out) ------------
__global__ void ln_kernel(const float* __restrict__ x,
                          const float* __restrict__ gamma,
                          const float* __restrict__ beta,
                          float* __restrict__ out) {
    int gw = (blockIdx.x * blockDim.x + threadIdx.x) >> 5;
    if (gw >= N_NODES) return;
    int lane = threadIdx.x & 31;
    int base = gw * 256 + lane * 8;

    float4 h1 = *(const float4*)&out[base];
    float4 h2 = *(const float4*)&out[base + 4];
    float4 x1 = *(const float4*)&x[base];
    float4 x2 = *(const float4*)&x[base + 4];
    float v[8];
    v[0] = h1.x + x1.x; v[1] = h1.y + x1.y; v[2] = h1.z + x1.z; v[3] = h1.w + x1.w;
    v[4] = h2.x + x2.x; v[5] = h2.y + x2.y; v[6] = h2.z + x2.z; v[7] = h2.w + x2.w;

    float s = 0.f, s2 = 0.f;
#pragma unroll
    for (int i = 0; i < 8; i++) { s += v[i]; s2 += v[i] * v[i]; }
#pragma unroll
    for (int off = 16; off > 0; off >>= 1) {
        s  += __shfl_xor_sync(0xffffffffu, s, off);
        s2 += __shfl_xor_sync(0xffffffffu, s2, off);
    }
    float mean = s * (1.f / 256.f);
    float var  = s2 * (1.f / 256.f) - mean * mean;
    float rs   = rsqrtf(var + 1e-5f);

    float4 g1 = *(const float4*)&gamma[lane * 8];
    float4 g2 = *(const float4*)&gamma[lane * 8 + 4];
    float4 be1 = *(const float4*)&beta[lane * 8];
    float4 be2 = *(const float4*)&beta[lane * 8 + 4];
    float4 o1, o2;
    o1.x = (v[0] - mean) * rs * g1.x + be1.x;
    o1.y = (v[1] - mean) * rs * g1.y + be1.y;
    o1.z = (v[2] - mean) * rs * g1.z + be1.z;
    o1.w = (v[3] - mean) * rs * g1.w + be1.w;
    o2.x = (v[4] - mean) * rs * g2.x + be2.x;
    o2.y = (v[5] - mean) * rs * g2.y + be2.y;
    o2.z = (v[6] - mean) * rs * g2.z + be2.z;
    o2.w = (v[7] - mean) * rs * g2.w + be2.w;
    *(float4*)&out[base]     = o1;
    *(float4*)&out[base + 4] = o2;
}

// ---------------- launch ----------------------------------------------------
extern "C" void kernel_launch(void* const* d_in, const int* in_sizes, int n_in,
                              void* d_out, int out_size) {
    const float* x     = (const float*)d_in[0];
    const int*   ei    = (const int*)d_in[1];      // int32 (JAX default x64-off)
    const float* W0    = (const float*)d_in[2];
    const float* as0   = (const float*)d_in[3];
    const float* ad0   = (const float*)d_in[4];
    const float* b0    = (const float*)d_in[5];
    const float* W1    = (const float*)d_in[6];
    const float* as1   = (const float*)d_in[7];
    const float* ad1   = (const float*)d_in[8];
    const float* b1    = (const float*)d_in[9];
    const float* gamma = (const float*)d_in[10];
    const float* beta  = (const float*)d_in[11];
    float* out = (float*)d_out;

    const int* row = ei;
    const int* col = ei + N_EDGES;

    zero_kernel<<<(TWO_N + 255) / 256, 256>>>();
    gemm_kernel<<<(N_NODES + 63) / 64, 256>>>(x, W0, W1);
    att_kernel<<<(N_NODES * 32 + 255) / 256, 256>>>(as0, ad0, as1, ad1);
    count_kernel<<<(N_EDGES + 255) / 256, 256>>>(row, col);
    scanA_kernel<<<SCAN_NBLK, SCAN_BLK>>>();
    scanB_kernel<<<1, 32>>>();
    scanC_kernel<<<SCAN_NBLK, SCAN_BLK>>>();
    scatter_kernel<<<(N_EDGES + 255) / 256, 256>>>(row, col);
    agg_kernel<<<(TWO_N * 32 + 255) / 256, 256>>>(b0, b1, out);
    ln_kernel<<<(N_NODES * 32 + 255) / 256, 256>>>(x, gamma, beta, out);
}

// round 4
// speedup vs baseline: 1.1649x; 1.1649x over previous
#include <cuda_runtime.h>

#define N_NODES 50000
#define N_EDGES 800000
#define TWO_N   100000
#define TWO_E   1600000
#define SCAN_BLK 1024
#define SCAN_NBLK ((TWO_N + SCAN_BLK - 1) / SCAN_BLK)   // 98

// ---------------- scratch ----------------------------------------------------
__device__ __align__(16) float g_xw[N_NODES * 256];  // x @ [W0 | W1] (51.2 MB)
__device__ __align__(16) float g_att[N_NODES * 32];  // per node: [s0(8) d0(8) s1(8) d1(8)]
__device__ int   g_deg[TWO_N];
__device__ int   g_off[TWO_N + 1];
__device__ int   g_cur[TWO_N];
__device__ int   g_srcarr[TWO_E];
__device__ int   g_bsum[SCAN_NBLK];
__device__ int   g_bsum_scan[SCAN_NBLK];

// ---------------- K0: zero degree counters ----------------------------------
__global__ void zero_kernel() {
    int i = blockIdx.x * blockDim.x + threadIdx.x;
    if (i < TWO_N) g_deg[i] = 0;
}

// ---------------- K1: GEMM + attention-logit epilogue ------------------------
// 64(M) x 256(N) tile, BK=16, 256 threads, 8x8/thread, reg-staged pipeline.
// warp rt owns rows rt*8..rt*8+7 fully (256 cols across 32 lanes) -> compute
// per-head attention logits inline (8-FMA partial + shfl_xor(1) pair reduce).
__global__ __launch_bounds__(256) void gemm_kernel(
        const float* __restrict__ x,
        const float* __restrict__ W0, const float* __restrict__ W1,
        const float* __restrict__ as0, const float* __restrict__ ad0,
        const float* __restrict__ as1, const float* __restrict__ ad1) {
    __shared__ float xs[16][68];    // [kk][row], padded
    __shared__ float ws[16][256];   // [kk][col]
    int tid = threadIdx.x;
    int m0  = blockIdx.x * 64;
    int ct  = tid & 31;
    int rt  = tid >> 5;

    // gmem-load mapping
    int xrow = tid >> 2;            // 0..63
    int xk4  = (tid & 3) * 4;       // 0,4,8,12
    int xgr  = m0 + xrow;
    bool xok = (xgr < N_NODES);

    float4 xr;                       // staged x tile (1 float4/thread)
    float4 wr[4];                    // staged w tile (4 float4/thread)

    // preload k0 = 0
    xr = xok ? *(const float4*)&x[xgr * 256 + xk4] : make_float4(0.f,0.f,0.f,0.f);
#pragma unroll
    for (int i = 0; i < 4; i++) {
        int idx4 = tid + 256 * i;
        int kk = idx4 >> 6, c4 = (idx4 & 63) * 4;
        wr[i] = (c4 < 128) ? *(const float4*)&W0[kk * 128 + c4]
                           : *(const float4*)&W1[kk * 128 + (c4 - 128)];
    }

    float acc[8][8];
#pragma unroll
    for (int r = 0; r < 8; r++)
#pragma unroll
        for (int c = 0; c < 8; c++) acc[r][c] = 0.f;

    for (int k0 = 0; k0 < 256; k0 += 16) {
        // stage regs -> smem
        xs[xk4 + 0][xrow] = xr.x;
        xs[xk4 + 1][xrow] = xr.y;
        xs[xk4 + 2][xrow] = xr.z;
        xs[xk4 + 3][xrow] = xr.w;
#pragma unroll
        for (int i = 0; i < 4; i++) {
            int idx4 = tid + 256 * i;
            int kk = idx4 >> 6, c4 = (idx4 & 63) * 4;
            *(float4*)&ws[kk][c4] = wr[i];
        }
        __syncthreads();

        // prefetch next K tile
        if (k0 + 16 < 256) {
            int kn = k0 + 16;
            xr = xok ? *(const float4*)&x[xgr * 256 + kn + xk4]
                     : make_float4(0.f,0.f,0.f,0.f);
#pragma unroll
            for (int i = 0; i < 4; i++) {
                int idx4 = tid + 256 * i;
                int kk = idx4 >> 6, c4 = (idx4 & 63) * 4;
                wr[i] = (c4 < 128) ? *(const float4*)&W0[(kn + kk) * 128 + c4]
                                   : *(const float4*)&W1[(kn + kk) * 128 + (c4 - 128)];
            }
        }

#pragma unroll
        for (int kk = 0; kk < 16; kk++) {
            float4 xa = *(const float4*)&xs[kk][rt * 8];
            float4 xb = *(const float4*)&xs[kk][rt * 8 + 4];
            float4 wa = *(const float4*)&ws[kk][ct * 8];
            float4 wb = *(const float4*)&ws[kk][ct * 8 + 4];
            float xv[8] = {xa.x, xa.y, xa.z, xa.w, xb.x, xb.y, xb.z, xb.w};
            float wv[8] = {wa.x, wa.y, wa.z, wa.w, wb.x, wb.y, wb.z, wb.w};
#pragma unroll
            for (int r = 0; r < 8; r++)
#pragma unroll
                for (int c = 0; c < 8; c++) acc[r][c] += xv[r] * wv[c];
        }
        __syncthreads();
    }

    // ---- store xw (thread covers cols ct*8..ct*8+7 of rows rt*8..+7) -------
#pragma unroll
    for (int r = 0; r < 8; r++) {
        int gr = m0 + rt * 8 + r;
        if (gr < N_NODES) {
            float4 o1 = make_float4(acc[r][0], acc[r][1], acc[r][2], acc[r][3]);
            float4 o2 = make_float4(acc[r][4], acc[r][5], acc[r][6], acc[r][7]);
            *(float4*)&g_xw[gr * 256 + ct * 8]     = o1;
            *(float4*)&g_xw[gr * 256 + ct * 8 + 4] = o2;
        }
    }

    // ---- attention logits ---------------------------------------------------
    // global cols ct*8..+7; hop = ct>>4; col-in-hop = (ct&15)*8+i (one head)
    int hop = ct >> 4;
    int lc  = (ct & 15) * 8;
    int h   = (ct & 15) >> 1;
    const float* asv = hop ? as1 : as0;
    const float* adv = hop ? ad1 : ad0;
    float4 sa = *(const float4*)&asv[lc];
    float4 sb = *(const float4*)&asv[lc + 4];
    float4 da = *(const float4*)&adv[lc];
    float4 db = *(const float4*)&adv[lc + 4];
    float as8[8] = {sa.x, sa.y, sa.z, sa.w, sb.x, sb.y, sb.z, sb.w};
    float ad8[8] = {da.x, da.y, da.z, da.w, db.x, db.y, db.z, db.w};
#pragma unroll
    for (int r = 0; r < 8; r++) {
        float ps = 0.f, pd = 0.f;
#pragma unroll
        for (int i = 0; i < 8; i++) {
            ps += acc[r][i] * as8[i];
            pd += acc[r][i] * ad8[i];
        }
        ps += __shfl_xor_sync(0xffffffffu, ps, 1);
        pd += __shfl_xor_sync(0xffffffffu, pd, 1);
        int gr = m0 + rt * 8 + r;
        if (!(ct & 1) && gr < N_NODES) {
            g_att[gr * 32 + hop * 16 + h]     = ps;
            g_att[gr * 32 + hop * 16 + 8 + h] = pd;
        }
    }
}

// ---------------- K2: count in-degrees (both hops) ---------------------------
__global__ void count_kernel(const int* __restrict__ row,
                             const int* __restrict__ col) {
    int e = blockIdx.x * blockDim.x + threadIdx.x;
    if (e >= N_EDGES) return;
    int d0 = col[e];
    atomicAdd(&g_deg[d0], 1);
    int d1 = col[d0];
    atomicAdd(&g_deg[N_NODES + d1], 1);
}

// ---------------- K3: exclusive scan (3 stages) ------------------------------
__global__ void scanA_kernel() {
    __shared__ int sh[SCAN_BLK];
    int t = threadIdx.x;
    int i = blockIdx.x * SCAN_BLK + t;
    int v = (i < TWO_N) ? g_deg[i] : 0;
    sh[t] = v;
    __syncthreads();
    for (int off = 1; off < SCAN_BLK; off <<= 1) {
        int add = (t >= off) ? sh[t - off] : 0;
        __syncthreads();
        sh[t] += add;
        __syncthreads();
    }
    if (i < TWO_N) g_off[i] = sh[t] - v;
    if (t == SCAN_BLK - 1) g_bsum[blockIdx.x] = sh[SCAN_BLK - 1];
}

__global__ void scanB_kernel() {        // parallel scan over 98 block sums
    __shared__ int sh[128];
    int t = threadIdx.x;
    int v = (t < SCAN_NBLK) ? g_bsum[t] : 0;
    sh[t] = v;
    __syncthreads();
    for (int off = 1; off < 128; off <<= 1) {
        int add = (t >= off) ? sh[t - off] : 0;
        __syncthreads();
        sh[t] += add;
        __syncthreads();
    }
    if (t < SCAN_NBLK) g_bsum_scan[t] = sh[t] - v;   // exclusive
}

__global__ void scanC_kernel() {
    int i = blockIdx.x * SCAN_BLK + threadIdx.x;
    if (i < TWO_N) {
        int v = g_off[i] + g_bsum_scan[blockIdx.x];
        g_off[i] = v;
        g_cur[i] = v;
    }
    if (i == 0) g_off[TWO_N] = TWO_E;
}

// ---------------- K4: scatter sources into CSR -------------------------------
__global__ void scatter_kernel(const int* __restrict__ row,
                               const int* __restrict__ col) {
    int e = blockIdx.x * blockDim.x + threadIdx.x;
    if (e >= N_EDGES) return;
    int r0 = row[e];
    int d0 = col[e];
    int p = atomicAdd(&g_cur[d0], 1);
    g_srcarr[p] = r0;
    int r1 = row[d0];
    int d1 = col[d0];
    p = atomicAdd(&g_cur[N_NODES + d1], 1);
    g_srcarr[p] = r1;
}

// ---------------- K5: fused aggregation (both hops) + residual + LayerNorm ---
// warp per node; lane covers 4 channels of hop0 (c0=lane*4) and the matching
// 4 channels of hop1 (128+c0). Self-loop analytic; hop1 self doubled
// (reference appends self-loops twice for hop 2). No segment-max: logits are
// O(1) so exp() is safe, and softmax is shift-invariant.
__global__ void agg_ln_kernel(const float* __restrict__ b0,
                              const float* __restrict__ b1,
                              const float* __restrict__ x,
                              const float* __restrict__ gamma,
                              const float* __restrict__ beta,
                              float* __restrict__ out) {
    int n = (blockIdx.x * blockDim.x + threadIdx.x) >> 5;
    if (n >= N_NODES) return;
    int lane = threadIdx.x & 31;
    int head = lane >> 2;
    int c0 = lane * 4;

    // ---- hop 0 ----
    float ad = g_att[n * 32 + 8 + head];
    float t  = g_att[n * 32 + head] + ad;
    t = (t > 0.f) ? t : 0.2f * t;
    float p = __expf(t);
    float sum0 = p;
    float4 v = *(const float4*)&g_xw[n * 256 + c0];
    float4 acc0 = make_float4(p * v.x, p * v.y, p * v.z, p * v.w);
    int je = g_off[n + 1];
    for (int j = g_off[n]; j < je; j++) {
        int src = g_srcarr[j];
        float tt = g_att[src * 32 + head] + ad;
        tt = (tt > 0.f) ? tt : 0.2f * tt;
        float pp = __expf(tt);
        sum0 += pp;
        float4 w = *(const float4*)&g_xw[src * 256 + c0];
        acc0.x += pp * w.x; acc0.y += pp * w.y;
        acc0.z += pp * w.z; acc0.w += pp * w.w;
    }

    // ---- hop 1 (self term doubled) ----
    ad = g_att[n * 32 + 24 + head];
    t  = g_att[n * 32 + 16 + head] + ad;
    t = (t > 0.f) ? t : 0.2f * t;
    p = 2.0f * __expf(t);
    float sum1 = p;
    v = *(const float4*)&g_xw[n * 256 + 128 + c0];
    float4 acc1 = make_float4(p * v.x, p * v.y, p * v.z, p * v.w);
    je = g_off[N_NODES + n + 1];
    for (int j = g_off[N_NODES + n]; j < je; j++) {
        int src = g_srcarr[j];
        float tt = g_att[src * 32 + 16 + head] + ad;
        tt = (tt > 0.f) ? tt : 0.2f * tt;
        float pp = __expf(tt);
        sum1 += pp;
        float4 w = *(const float4*)&g_xw[src * 256 + 128 + c0];
        acc1.x += pp * w.x; acc1.y += pp * w.y;
        acc1.z += pp * w.z; acc1.w += pp * w.w;
    }

    // ---- bias + residual ----
    float i0 = 1.f / sum0, i1 = 1.f / sum1;
    float4 bb0 = *(const float4*)&b0[c0];
    float4 bb1 = *(const float4*)&b1[c0];
    float4 x0 = *(const float4*)&x[n * 256 + c0];
    float4 x1 = *(const float4*)&x[n * 256 + 128 + c0];
    float vv[8];
    vv[0] = acc0.x * i0 + bb0.x + x0.x;
    vv[1] = acc0.y * i0 + bb0.y + x0.y;
    vv[2] = acc0.z * i0 + bb0.z + x0.z;
    vv[3] = acc0.w * i0 + bb0.w + x0.w;
    vv[4] = acc1.x * i1 + bb1.x + x1.x;
    vv[5] = acc1.y * i1 + bb1.y + x1.y;
    vv[6] = acc1.z * i1 + bb1.z + x1.z;
    vv[7] = acc1.w * i1 + bb1.w + x1.w;

    // ---- LayerNorm over 256 channels (8/lane) ----
    float s = 0.f, s2 = 0.f;
#pragma unroll
    for (int i = 0; i < 8; i++) { s += vv[i]; s2 += vv[i] * vv[i]; }
#pragma unroll
    for (int off = 16; off > 0; off >>= 1) {
        s  += __shfl_xor_sync(0xffffffffu, s, off);
        s2 += __shfl_xor_sync(0xffffffffu, s2, off);
    }
    float mean = s * (1.f / 256.f);
    float var  = s2 * (1.f / 256.f) - mean * mean;
    float rs   = rsqrtf(var + 1e-5f);

    float4 g0 = *(const float4*)&gamma[c0];
    float4 g1 = *(const float4*)&gamma[128 + c0];
    float4 be0 = *(const float4*)&beta[c0];
    float4 be1 = *(const float4*)&beta[128 + c0];
    float4 o0, o1;
    o0.x = (vv[0] - mean) * rs * g0.x + be0.x;
    o0.y = (vv[1] - mean) * rs * g0.y + be0.y;
    o0.z = (vv[2] - mean) * rs * g0.z + be0.z;
    o0.w = (vv[3] - mean) * rs * g0.w + be0.w;
    o1.x = (vv[4] - mean) * rs * g1.x + be1.x;
    o1.y = (vv[5] - mean) * rs * g1.y + be1.y;
    o1.z = (vv[6] - mean) * rs * g1.z + be1.z;
    o1.w = (vv[7] - mean) * rs * g1.w + be1.w;
    *(float4*)&out[n * 256 + c0]       = o0;
    *(float4*)&out[n * 256 + 128 + c0] = o1;
}

// ---------------- launch -----------------------------------------------------
extern "C" void kernel_launch(void* const* d_in, const int* in_sizes, int n_in,
                              void* d_out, int out_size) {
    const float* x     = (const float*)d_in[0];
    const int*   ei    = (const int*)d_in[1];      // int32 (JAX x64 off)
    const float* W0    = (const float*)d_in[2];
    const float* as0   = (const float*)d_in[3];
    const float* ad0   = (const float*)d_in[4];
    const float* b0    = (const float*)d_in[5];
    const float* W1    = (const float*)d_in[6];
    const float* as1   = (const float*)d_in[7];
    const float* ad1   = (const float*)d_in[8];
    const float* b1    = (const float*)d_in[9];
    const float* gamma = (const float*)d_in[10];
    const float* beta  = (const float*)d_in[11];
    float* out = (float*)d_out;

    const int* row = ei;
    const int* col = ei + N_EDGES;

    zero_kernel<<<(TWO_N + 255) / 256, 256>>>();
    gemm_kernel<<<(N_NODES + 63) / 64, 256>>>(x, W0, W1, as0, ad0, as1, ad1);
    count_kernel<<<(N_EDGES + 255) / 256, 256>>>(row, col);
    scanA_kernel<<<SCAN_NBLK, SCAN_BLK>>>();
    scanB_kernel<<<1, 128>>>();
    scanC_kernel<<<SCAN_NBLK, SCAN_BLK>>>();
    scatter_kernel<<<(N_EDGES + 255) / 256, 256>>>(row, col);
    agg_ln_kernel<<<(N_NODES * 32 + 255) / 256, 256>>>(b0, b1, x, gamma, beta, out);
}

// round 6
// speedup vs baseline: 1.8049x; 1.5494x over previous
#include <cuda_runtime.h>
#include <cuda_bf16.h>
#include <cstdint>

#define N_NODES 50000
#define N_EDGES 800000
#define TWO_N   100000
#define TWO_E   1600000
#define SCAN_BLK 1024
#define SCAN_NBLK ((TWO_N + SCAN_BLK - 1) / SCAN_BLK)   // 98

// ---------------- scratch ----------------------------------------------------
__device__ __align__(16) float g_xw[N_NODES * 256];   // x @ [W0 | W1]
__device__ __align__(16) float g_att[N_NODES * 32];   // [s0(8) d0(8) s1(8) d1(8)]
__device__ __align__(16) __nv_bfloat16 g_Whi[256 * 256];  // [k][n] n: [W0|W1]
__device__ __align__(16) __nv_bfloat16 g_Wlo[256 * 256];
__device__ int   g_deg[TWO_N];
__device__ int   g_off[TWO_N + 1];
__device__ int   g_cur[TWO_N];
__device__ int   g_srcarr[TWO_E];
__device__ int   g_bsum[SCAN_NBLK];
__device__ int   g_bsum_scan[SCAN_NBLK];

__device__ __forceinline__ uint32_t smem_u32(const void* p) {
    uint32_t a;
    asm("{ .reg .u64 t; cvta.to.shared.u64 t, %1; cvt.u32.u64 %0, t; }"
        : "=r"(a) : "l"(p));
    return a;
}

// ---------------- W split kernel ---------------------------------------------
__global__ void wsplit_kernel(const float* __restrict__ W0,
                              const float* __restrict__ W1) {
    int i = blockIdx.x * 256 + threadIdx.x;      // over [k][n], n in [0,256)
    int k = i >> 8, n = i & 255;
    float v = (n < 128) ? W0[k * 128 + n] : W1[k * 128 + (n - 128)];
    __nv_bfloat16 h = __float2bfloat16(v);
    g_Whi[i] = h;
    g_Wlo[i] = __float2bfloat16(v - __bfloat162float(h));
}

// ---------------- HMMA GEMM (split-bf16, 3 terms) + logits epilogue ----------
// CTA: 128(M) x 128(N); blockIdx.y = hop (n half). 8 warps, warp tile 32x64.
// K chunked by 32 through smem. mma.sync m16n8k16 bf16 (portable HMMA path).
#define APAD 40     // 32 + 8 bf16
#define BPAD 136    // 128 + 8 bf16

__global__ __launch_bounds__(256) void gemm_hmma_kernel(
        const float* __restrict__ x,
        const float* __restrict__ as0, const float* __restrict__ ad0,
        const float* __restrict__ as1, const float* __restrict__ ad1) {
    __shared__ __nv_bfloat16 sAh[128][APAD];
    __shared__ __nv_bfloat16 sAl[128][APAD];
    __shared__ __nv_bfloat16 sBh[32][BPAD];
    __shared__ __nv_bfloat16 sBl[32][BPAD];

    int tid  = threadIdx.x;
    int wid  = tid >> 5;
    int lane = tid & 31;
    int m0   = blockIdx.x * 128;
    int half = blockIdx.y;               // 0: hop0 cols, 1: hop1 cols
    int m0w  = (wid >> 1) * 32;          // warp M offset in tile
    int n0w  = (wid & 1) * 64;           // warp N offset in tile (within 128)

    float acc[2][8][4];
#pragma unroll
    for (int a = 0; a < 2; a++)
#pragma unroll
        for (int b = 0; b < 8; b++)
#pragma unroll
            for (int c = 0; c < 4; c++) acc[a][b][c] = 0.f;

    // loader mappings
    int arow = tid >> 1, akb = (tid & 1) * 16;       // A: row, k-base
    bool aok = (m0 + arow) < N_NODES;
    int bk = tid >> 3, bnb = (tid & 7) * 16;         // B: k, n-base

    // per-lane ldmatrix addresses (fixed across chunks except k0 offset)
    int a_roff = ((lane >> 3) & 1) * 8 + (lane & 7);
    int a_coff = ((lane >> 4) & 1) * 8;
    int b_koff = ((lane >> 3) & 1) * 8 + (lane & 7);
    int b_noff = ((lane >> 4) & 1) * 8;

    for (int kc = 0; kc < 8; kc++) {
        if (kc > 0) __syncthreads();
        // ---- load A chunk: x[m0..+127][kc*32 .. +31] -> hi/lo bf16 ----
        {
            const float* src = x + (size_t)(m0 + arow) * 256 + kc * 32 + akb;
#pragma unroll
            for (int i = 0; i < 16; i += 4) {
                float4 v = aok ? *(const float4*)(src + i)
                               : make_float4(0.f, 0.f, 0.f, 0.f);
                float fv[4] = {v.x, v.y, v.z, v.w};
                uint32_t ph[2], pl[2];
#pragma unroll
                for (int j = 0; j < 2; j++) {
                    __nv_bfloat16 h0 = __float2bfloat16(fv[2*j]);
                    __nv_bfloat16 h1 = __float2bfloat16(fv[2*j+1]);
                    __nv_bfloat16 l0 = __float2bfloat16(fv[2*j]   - __bfloat162float(h0));
                    __nv_bfloat16 l1 = __float2bfloat16(fv[2*j+1] - __bfloat162float(h1));
                    ph[j] = (uint32_t)__bfloat16_as_ushort(h0)
                          | ((uint32_t)__bfloat16_as_ushort(h1) << 16);
                    pl[j] = (uint32_t)__bfloat16_as_ushort(l0)
                          | ((uint32_t)__bfloat16_as_ushort(l1) << 16);
                }
                *(uint2*)&sAh[arow][akb + i] = make_uint2(ph[0], ph[1]);
                *(uint2*)&sAl[arow][akb + i] = make_uint2(pl[0], pl[1]);
            }
        }
        // ---- load B chunk: g_W{hi,lo}[kc*32+bk][half*128 + bnb ..+15] ----
        {
            const __nv_bfloat16* wh = g_Whi + (size_t)(kc * 32 + bk) * 256 + half * 128 + bnb;
            const __nv_bfloat16* wl = g_Wlo + (size_t)(kc * 32 + bk) * 256 + half * 128 + bnb;
            uint4 vh0 = *(const uint4*)wh;          // 8 bf16
            uint4 vh1 = *(const uint4*)(wh + 8);
            uint4 vl0 = *(const uint4*)wl;
            uint4 vl1 = *(const uint4*)(wl + 8);
            *(uint4*)&sBh[bk][bnb]     = vh0;
            *(uint4*)&sBh[bk][bnb + 8] = vh1;
            *(uint4*)&sBl[bk][bnb]     = vl0;
            *(uint4*)&sBl[bk][bnb + 8] = vl1;
        }
        __syncthreads();

        // ---- mma phase: 2 k-steps of 16 ----
#pragma unroll
        for (int ks = 0; ks < 2; ks++) {
            int k0 = ks * 16;
            uint32_t ah[2][4], al[2][4], bb[4][4];
            // A fragments (hi & lo), tiles mt = 0,1
#pragma unroll
            for (int mt = 0; mt < 2; mt++) {
                uint32_t adrh = smem_u32(&sAh[m0w + mt * 16 + a_roff][k0 + a_coff]);
                asm volatile("ldmatrix.sync.aligned.m8n8.x4.shared.b16 {%0,%1,%2,%3}, [%4];"
                    : "=r"(ah[mt][0]), "=r"(ah[mt][1]), "=r"(ah[mt][2]), "=r"(ah[mt][3])
                    : "r"(adrh));
                uint32_t adrl = smem_u32(&sAl[m0w + mt * 16 + a_roff][k0 + a_coff]);
                asm volatile("ldmatrix.sync.aligned.m8n8.x4.shared.b16 {%0,%1,%2,%3}, [%4];"
                    : "=r"(al[mt][0]), "=r"(al[mt][1]), "=r"(al[mt][2]), "=r"(al[mt][3])
                    : "r"(adrl));
            }
            // B hi fragments: 4 pairs of n-tiles
#pragma unroll
            for (int p = 0; p < 4; p++) {
                uint32_t adr = smem_u32(&sBh[k0 + b_koff][n0w + p * 16 + b_noff]);
                asm volatile("ldmatrix.sync.aligned.m8n8.x4.trans.shared.b16 {%0,%1,%2,%3}, [%4];"
                    : "=r"(bb[p][0]), "=r"(bb[p][1]), "=r"(bb[p][2]), "=r"(bb[p][3])
                    : "r"(adr));
            }
            // terms 1 & 3: Ah*Bh, Al*Bh
#pragma unroll
            for (int mt = 0; mt < 2; mt++)
#pragma unroll
                for (int nt = 0; nt < 8; nt++) {
                    uint32_t b0 = bb[nt >> 1][(nt & 1) * 2];
                    uint32_t b1 = bb[nt >> 1][(nt & 1) * 2 + 1];
                    float* d = acc[mt][nt];
                    asm volatile(
                        "mma.sync.aligned.m16n8k16.row.col.f32.bf16.bf16.f32 "
                        "{%0,%1,%2,%3}, {%4,%5,%6,%7}, {%8,%9}, {%0,%1,%2,%3};"
                        : "+f"(d[0]), "+f"(d[1]), "+f"(d[2]), "+f"(d[3])
                        : "r"(ah[mt][0]), "r"(ah[mt][1]), "r"(ah[mt][2]), "r"(ah[mt][3]),
                          "r"(b0), "r"(b1));
                    asm volatile(
                        "mma.sync.aligned.m16n8k16.row.col.f32.bf16.bf16.f32 "
                        "{%0,%1,%2,%3}, {%4,%5,%6,%7}, {%8,%9}, {%0,%1,%2,%3};"
                        : "+f"(d[0]), "+f"(d[1]), "+f"(d[2]), "+f"(d[3])
                        : "r"(al[mt][0]), "r"(al[mt][1]), "r"(al[mt][2]), "r"(al[mt][3]),
                          "r"(b0), "r"(b1));
                }
            // B lo fragments (reuse bb), term 2: Ah*Bl
#pragma unroll
            for (int p = 0; p < 4; p++) {
                uint32_t adr = smem_u32(&sBl[k0 + b_koff][n0w + p * 16 + b_noff]);
                asm volatile("ldmatrix.sync.aligned.m8n8.x4.trans.shared.b16 {%0,%1,%2,%3}, [%4];"
                    : "=r"(bb[p][0]), "=r"(bb[p][1]), "=r"(bb[p][2]), "=r"(bb[p][3])
                    : "r"(adr));
            }
#pragma unroll
            for (int mt = 0; mt < 2; mt++)
#pragma unroll
                for (int nt = 0; nt < 8; nt++) {
                    uint32_t b0 = bb[nt >> 1][(nt & 1) * 2];
                    uint32_t b1 = bb[nt >> 1][(nt & 1) * 2 + 1];
                    float* d = acc[mt][nt];
                    asm volatile(
                        "mma.sync.aligned.m16n8k16.row.col.f32.bf16.bf16.f32 "
                        "{%0,%1,%2,%3}, {%4,%5,%6,%7}, {%8,%9}, {%0,%1,%2,%3};"
                        : "+f"(d[0]), "+f"(d[1]), "+f"(d[2]), "+f"(d[3])
                        : "r"(ah[mt][0]), "r"(ah[mt][1]), "r"(ah[mt][2]), "r"(ah[mt][3]),
                          "r"(b0), "r"(b1));
                }
        }
    }

    // ---- epilogue: store xw + attention logits ----
    // acc[mt][nt]: rows r0 = m0+m0w+mt*16+(lane>>2), r1 = r0+8;
    //              cols (global) = half*128 + n0w + nt*8 + (lane&3)*2 + {0,1}
#pragma unroll
    for (int mt = 0; mt < 2; mt++) {
        int r0 = m0 + m0w + mt * 16 + (lane >> 2);
        int r1 = r0 + 8;
        bool ok0 = r0 < N_NODES, ok1 = r1 < N_NODES;
#pragma unroll
        for (int nt = 0; nt < 8; nt++) {
            int col = half * 128 + n0w + nt * 8 + (lane & 3) * 2;
            if (ok0) *(float2*)&g_xw[(size_t)r0 * 256 + col] =
                make_float2(acc[mt][nt][0], acc[mt][nt][1]);
            if (ok1) *(float2*)&g_xw[(size_t)r1 * 256 + col] =
                make_float2(acc[mt][nt][2], acc[mt][nt][3]);
        }
    }

    // logits
    const float* asv = half ? as1 : as0;
    const float* adv = half ? ad1 : ad0;
    float asr[16], adr_[16];
#pragma unroll
    for (int nt = 0; nt < 8; nt++) {
        int c = n0w + nt * 8 + (lane & 3) * 2;
        asr[nt * 2]     = asv[c];
        asr[nt * 2 + 1] = asv[c + 1];
        adr_[nt * 2]     = adv[c];
        adr_[nt * 2 + 1] = adv[c + 1];
    }
#pragma unroll
    for (int mt = 0; mt < 2; mt++) {
#pragma unroll
        for (int rh = 0; rh < 2; rh++) {
            float ps[4] = {0.f, 0.f, 0.f, 0.f};
            float pd[4] = {0.f, 0.f, 0.f, 0.f};
#pragma unroll
            for (int nt = 0; nt < 8; nt++) {
                int h = nt >> 1;
                float a0 = acc[mt][nt][rh * 2];
                float a1 = acc[mt][nt][rh * 2 + 1];
                ps[h] += a0 * asr[nt * 2] + a1 * asr[nt * 2 + 1];
                pd[h] += a0 * adr_[nt * 2] + a1 * adr_[nt * 2 + 1];
            }
#pragma unroll
            for (int off = 1; off < 4; off <<= 1) {
#pragma unroll
                for (int h = 0; h < 4; h++) {
                    ps[h] += __shfl_xor_sync(0xffffffffu, ps[h], off);
                    pd[h] += __shfl_xor_sync(0xffffffffu, pd[h], off);
                }
            }
            int r = m0 + m0w + mt * 16 + rh * 8 + (lane >> 2);
            if ((lane & 3) == 0 && r < N_NODES) {
#pragma unroll
                for (int h = 0; h < 4; h++) {
                    int gh = (n0w >> 4) + h;
                    g_att[r * 32 + half * 16 + gh]     = ps[h];
                    g_att[r * 32 + half * 16 + 8 + gh] = pd[h];
                }
            }
        }
    }
}

// ---------------- K0: zero degree counters ----------------------------------
__global__ void zero_kernel() {
    int i = blockIdx.x * blockDim.x + threadIdx.x;
    if (i < TWO_N) g_deg[i] = 0;
}

// ---------------- count in-degrees (both hops) -------------------------------
__global__ void count_kernel(const int* __restrict__ row,
                             const int* __restrict__ col) {
    int e = blockIdx.x * blockDim.x + threadIdx.x;
    if (e >= N_EDGES) return;
    int d0 = col[e];
    atomicAdd(&g_deg[d0], 1);
    int d1 = col[d0];
    atomicAdd(&g_deg[N_NODES + d1], 1);
}

// ---------------- exclusive scan (3 stages) ----------------------------------
__global__ void scanA_kernel() {
    __shared__ int sh[SCAN_BLK];
    int t = threadIdx.x;
    int i = blockIdx.x * SCAN_BLK + t;
    int v = (i < TWO_N) ? g_deg[i] : 0;
    sh[t] = v;
    __syncthreads();
    for (int off = 1; off < SCAN_BLK; off <<= 1) {
        int add = (t >= off) ? sh[t - off] : 0;
        __syncthreads();
        sh[t] += add;
        __syncthreads();
    }
    if (i < TWO_N) g_off[i] = sh[t] - v;
    if (t == SCAN_BLK - 1) g_bsum[blockIdx.x] = sh[SCAN_BLK - 1];
}

__global__ void scanB_kernel() {
    __shared__ int sh[128];
    int t = threadIdx.x;
    int v = (t < SCAN_NBLK) ? g_bsum[t] : 0;
    sh[t] = v;
    __syncthreads();
    for (int off = 1; off < 128; off <<= 1) {
        int add = (t >= off) ? sh[t - off] : 0;
        __syncthreads();
        sh[t] += add;
        __syncthreads();
    }
    if (t < SCAN_NBLK) g_bsum_scan[t] = sh[t] - v;
}

__global__ void scanC_kernel() {
    int i = blockIdx.x * SCAN_BLK + threadIdx.x;
    if (i < TWO_N) {
        int v = g_off[i] + g_bsum_scan[blockIdx.x];
        g_off[i] = v;
        g_cur[i] = v;
    }
    if (i == 0) g_off[TWO_N] = TWO_E;
}

// ---------------- scatter sources into CSR -----------------------------------
__global__ void scatter_kernel(const int* __restrict__ row,
                               const int* __restrict__ col) {
    int e = blockIdx.x * blockDim.x + threadIdx.x;
    if (e >= N_EDGES) return;
    int r0 = row[e];
    int d0 = col[e];
    int p = atomicAdd(&g_cur[d0], 1);
    g_srcarr[p] = r0;
    int r1 = row[d0];
    int d1 = col[d0];
    p = atomicAdd(&g_cur[N_NODES + d1], 1);
    g_srcarr[p] = r1;
}

// ---------------- fused aggregation + residual + LayerNorm -------------------
__global__ void agg_ln_kernel(const float* __restrict__ b0,
                              const float* __restrict__ b1,
                              const float* __restrict__ x,
                              const float* __restrict__ gamma,
                              const float* __restrict__ beta,
                              float* __restrict__ out) {
    int n = (blockIdx.x * blockDim.x + threadIdx.x) >> 5;
    if (n >= N_NODES) return;
    int lane = threadIdx.x & 31;
    int head = lane >> 2;
    int c0 = lane * 4;

    // ---- hop 0 ----
    float ad = g_att[n * 32 + 8 + head];
    float t  = g_att[n * 32 + head] + ad;
    t = (t > 0.f) ? t : 0.2f * t;
    float p = __expf(t);
    float sum0 = p;
    float4 v = *(const float4*)&g_xw[n * 256 + c0];
    float4 acc0 = make_float4(p * v.x, p * v.y, p * v.z, p * v.w);
    int je = g_off[n + 1];
    for (int j = g_off[n]; j < je; j++) {
        int src = g_srcarr[j];
        float tt = g_att[src * 32 + head] + ad;
        tt = (tt > 0.f) ? tt : 0.2f * tt;
        float pp = __expf(tt);
        sum0 += pp;
        float4 w = *(const float4*)&g_xw[src * 256 + c0];
        acc0.x += pp * w.x; acc0.y += pp * w.y;
        acc0.z += pp * w.z; acc0.w += pp * w.w;
    }

    // ---- hop 1 (self doubled: reference appends self-loops twice) ----
    ad = g_att[n * 32 + 24 + head];
    t  = g_att[n * 32 + 16 + head] + ad;
    t = (t > 0.f) ? t : 0.2f * t;
    p = 2.0f * __expf(t);
    float sum1 = p;
    v = *(const float4*)&g_xw[n * 256 + 128 + c0];
    float4 acc1 = make_float4(p * v.x, p * v.y, p * v.z, p * v.w);
    je = g_off[N_NODES + n + 1];
    for (int j = g_off[N_NODES + n]; j < je; j++) {
        int src = g_srcarr[j];
        float tt = g_att[src * 32 + 16 + head] + ad;
        tt = (tt > 0.f) ? tt : 0.2f * tt;
        float pp = __expf(tt);
        sum1 += pp;
        float4 w = *(const float4*)&g_xw[src * 256 + 128 + c0];
        acc1.x += pp * w.x; acc1.y += pp * w.y;
        acc1.z += pp * w.z; acc1.w += pp * w.w;
    }

    // ---- bias + residual + LN ----
    float i0 = 1.f / sum0, i1 = 1.f / sum1;
    float4 bb0 = *(const float4*)&b0[c0];
    float4 bb1 = *(const float4*)&b1[c0];
    float4 x0 = *(const float4*)&x[n * 256 + c0];
    float4 x1 = *(const float4*)&x[n * 256 + 128 + c0];
    float vv[8];
    vv[0] = acc0.x * i0 + bb0.x + x0.x;
    vv[1] = acc0.y * i0 + bb0.y + x0.y;
    vv[2] = acc0.z * i0 + bb0.z + x0.z;
    vv[3] = acc0.w * i0 + bb0.w + x0.w;
    vv[4] = acc1.x * i1 + bb1.x + x1.x;
    vv[5] = acc1.y * i1 + bb1.y + x1.y;
    vv[6] = acc1.z * i1 + bb1.z + x1.z;
    vv[7] = acc1.w * i1 + bb1.w + x1.w;

    float s = 0.f, s2 = 0.f;
#pragma unroll
    for (int i = 0; i < 8; i++) { s += vv[i]; s2 += vv[i] * vv[i]; }
#pragma unroll
    for (int off = 16; off > 0; off >>= 1) {
        s  += __shfl_xor_sync(0xffffffffu, s, off);
        s2 += __shfl_xor_sync(0xffffffffu, s2, off);
    }
    float mean = s * (1.f / 256.f);
    float var  = s2 * (1.f / 256.f) - mean * mean;
    float rs   = rsqrtf(var + 1e-5f);

    float4 g0 = *(const float4*)&gamma[c0];
    float4 g1 = *(const float4*)&gamma[128 + c0];
    float4 be0 = *(const float4*)&beta[c0];
    float4 be1 = *(const float4*)&beta[128 + c0];
    float4 o0, o1;
    o0.x = (vv[0] - mean) * rs * g0.x + be0.x;
    o0.y = (vv[1] - mean) * rs * g0.y + be0.y;
    o0.z = (vv[2] - mean) * rs * g0.z + be0.z;
    o0.w = (vv[3] - mean) * rs * g0.w + be0.w;
    o1.x = (vv[4] - mean) * rs * g1.x + be1.x;
    o1.y = (vv[5] - mean) * rs * g1.y + be1.y;
    o1.z = (vv[6] - mean) * rs * g1.z + be1.z;
    o1.w = (vv[7] - mean) * rs * g1.w + be1.w;
    *(float4*)&out[n * 256 + c0]       = o0;
    *(float4*)&out[n * 256 + 128 + c0] = o1;
}

// ---------------- launch -----------------------------------------------------
extern "C" void kernel_launch(void* const* d_in, const int* in_sizes, int n_in,
                              void* d_out, int out_size) {
    const float* x     = (const float*)d_in[0];
    const int*   ei    = (const int*)d_in[1];
    const float* W0    = (const float*)d_in[2];
    const float* as0   = (const float*)d_in[3];
    const float* ad0   = (const float*)d_in[4];
    const float* b0    = (const float*)d_in[5];
    const float* W1    = (const float*)d_in[6];
    const float* as1   = (const float*)d_in[7];
    const float* ad1   = (const float*)d_in[8];
    const float* b1    = (const float*)d_in[9];
    const float* gamma = (const float*)d_in[10];
    const float* beta  = (const float*)d_in[11];
    float* out = (float*)d_out;

    const int* row = ei;
    const int* col = ei + N_EDGES;

    zero_kernel<<<(TWO_N + 255) / 256, 256>>>();
    wsplit_kernel<<<256, 256>>>(W0, W1);
    gemm_hmma_kernel<<<dim3((N_NODES + 127) / 128, 2), 256>>>(x, as0, ad0, as1, ad1);
    count_kernel<<<(N_EDGES + 255) / 256, 256>>>(row, col);
    scanA_kernel<<<SCAN_NBLK, SCAN_BLK>>>();
    scanB_kernel<<<1, 128>>>();
    scanC_kernel<<<SCAN_NBLK, SCAN_BLK>>>();
    scatter_kernel<<<(N_EDGES + 255) / 256, 256>>>(row, col);
    agg_ln_kernel<<<(N_NODES * 32 + 255) / 256, 256>>>(b0, b1, x, gamma, beta, out);
}